// round 8
// baseline (speedup 1.0000x reference)
#include <cuda_runtime.h>
#include <cstdint>

#define BB 32
#define T_IN 512
#define NT 426
#define NC 1629          // 543*3
#define JF 53
#define XPART ((size_t)BB * NT * NC)   // 22,206,528
#define NCHUNK 7         // 7*256 = 1792 >= 1629
#define TT 4             // t-tile per block
#define TILES 107        // ceil(426/4)

__device__ __forceinline__ bool read_bool_m(const void* p, int i, int m) {
    if (m == 0) return ((const unsigned char*)p)[i] != 0;
    if (m == 1) return ((const int*)p)[i] != 0;
    return ((const float*)p)[i] != 0.0f;
}

// Single fused kernel. grid = BB * TILES, block = 256.
// Per block: dtype detect (128-word window), ballot scan of this batch's
// keep mask -> kept list in shared, TT weight-list setups, then TT streaming
// passes out[b,t,:] = sum_i w_i * x[b,row_i,:] + noise*.01 + spatial*.005.
// Adjacent t share x rows -> L1/L2 reuse (this kernel is LTS-cap limited).
__global__ __launch_bounds__(256) void fused_kernel(
    const float* __restrict__ x,
    const void*  __restrict__ mask,
    const void*  __restrict__ keep,
    const float* __restrict__ bj,
    const float* __restrict__ noise,
    const float* __restrict__ sp,
    float* __restrict__ out)
{
    __shared__ int   s_bad, s_anyf, s_mode;
    __shared__ int   s_kept[NT];
    __shared__ int   s_K;
    __shared__ int   wsum[16];
    __shared__ int   srows[TT][8];
    __shared__ float sw[TT][8];
    __shared__ int   sn[TT];

    const int blk  = blockIdx.x;
    const int b    = blk / TILES;
    const int t0   = (blk % TILES) * TT;
    const int tid  = threadIdx.x;

    // ---- phase 1: dtype detection (128-word window; unambiguous:
    //  uint8-packed: some word has a 0x01 byte beyond bit0 -> bad01, never 0x3F800000
    //  int32 0/1   : all words in {0,1}
    //  float32     : contains 0x3F800000 -> bad01 + anyf) ----
    if (tid == 0) { s_bad = 0; s_anyf = 0; }
    __syncthreads();
    if (tid < 128) {
        unsigned v = ((const unsigned*)keep)[tid];
        if (v != 0u && v != 1u) atomicOr(&s_bad, 1);
        if (v == 0x3F800000u)   atomicOr(&s_anyf, 1);
    }
    __syncthreads();
    if (tid == 0) s_mode = s_bad ? (s_anyf ? 2 : 0) : 1;
    __syncthreads();
    const int m = s_mode;

    // ---- phase 2: kept-index scan over this batch (2 ballot rounds) ----
    {
        int lane = tid & 31, wid = tid >> 5;
        // round 0: t = tid (0..255)
        bool k0 = read_bool_m(keep, b * NT + tid, m);
        unsigned bal0 = __ballot_sync(0xFFFFFFFFu, k0);
        if (lane == 0) wsum[wid] = __popc(bal0);
        // round 1: t = 256 + tid (256..425)
        int t1 = 256 + tid;
        bool k1 = (t1 < NT) ? read_bool_m(keep, b * NT + t1, m) : false;
        unsigned bal1 = __ballot_sync(0xFFFFFFFFu, k1);
        if (lane == 0) wsum[8 + wid] = __popc(bal1);
        __syncthreads();
        int pre0 = __popc(bal0 & ((1u << lane) - 1u));
        int pre1 = __popc(bal1 & ((1u << lane) - 1u));
        int base0 = 0, base1 = 0;
        for (int i = 0; i < wid; i++)     base0 += wsum[i];
        for (int i = 0; i < 8 + wid; i++) base1 += wsum[i];
        if (k0) s_kept[base0 + pre0] = tid;
        if (k1) s_kept[base1 + pre1] = t1;
        if (tid == 0) {
            int K = 0;
            for (int i = 0; i < 16; i++) K += wsum[i];
            s_K = K;
        }
        __syncthreads();
    }

    // ---- phase 3: setup for TT t's (threads 0..TT-1) + mask outputs ----
    if (tid < TT) {
        int t = t0 + tid;
        if (t < NT) {
            int bt = b * NT + t;
            int K = s_K;
            bool kb = read_bool_m(keep, bt, m);

            // mask output
            int nidx = (int)floorf((float)t * (512.0f / 426.0f));
            if (nidx > T_IN - 1) nidx = T_IN - 1;
            bool mo = read_bool_m(mask, b * T_IN + nidx, m) && kb;
            out[XPART + (size_t)bt] = mo ? 1.0f : 0.0f;

            // jitter (scale-then-lerp matches reference rounding)
            float jit = 0.0f;
            if (t > 0) {
                float sj = (float)t * (52.0f / 425.0f);
                int ij = (int)floorf(sj);
                if (ij > JF - 2) ij = JF - 2;
                if (ij < 0) ij = 0;
                float fj = sj - (float)ij;
                float j0 = bj[b * JF + ij]     * 0.02f;
                float j1 = bj[b * JF + ij + 1] * 0.02f;
                jit = j0 * (1.0f - fj) + j1 * fj;
            }

            int   rows[8];
            float wv[8];
            int n = 0;

            auto push = [&](int r, float w) {
                for (int i = 0; i < n; i++)
                    if (rows[i] == r) { wv[i] += w; return; }
                rows[n] = r; wv[n] = w; n++;
            };
            auto add_x1 = [&](int tau, float c) {
                float s = (float)tau * (511.0f / 425.0f);
                int i0 = (int)floorf(s);
                if (i0 > T_IN - 2) i0 = T_IN - 2;
                if (i0 < 0) i0 = 0;
                float f = s - (float)i0;
                push(i0,     c * (1.0f - f));
                push(i0 + 1, c * f);
            };
            auto add_x2 = [&](int tau, float c) {
                if (read_bool_m(keep, b * NT + tau, m)) {
                    add_x1(tau, c);
                } else {
                    float s = ((float)tau * (float)(K - 1)) / 425.0f;
                    int r0 = (int)floorf(s);
                    if (r0 > K - 2) r0 = K - 2;
                    if (r0 < 0) r0 = 0;
                    float fd = s - (float)r0;
                    add_x1(s_kept[r0],     c * (1.0f - fd));
                    add_x1(s_kept[r0 + 1], c * fd);
                }
            };

            if (t == 0) {
                add_x2(0, 1.0f);
            } else {
                add_x2(t,     1.0f + jit);
                add_x2(t - 1, -jit);
            }
            sn[tid] = n;
            #pragma unroll
            for (int i = 0; i < 8; i++) {
                srows[tid][i] = (i < n) ? rows[i] : 0;
                sw[tid][i]    = (i < n) ? wv[i]   : 0.0f;
            }
        } else {
            sn[tid] = 0;
        }
    }
    __syncthreads();

    // ---- phase 4: streaming passes (x rows reused across tt via L1/L2) ----
    const float* xb = x  + (size_t)b * T_IN * NC;
    const float* sb = sp + (size_t)b * NC;

    #pragma unroll 1
    for (int tt = 0; tt < TT; tt++) {
        int t = t0 + tt;
        if (t >= NT) break;
        int bt = b * NT + t;
        int n = sn[tt];
        const float* nz = noise + (size_t)bt * NC;
        float*       ob = out   + (size_t)bt * NC;

        float acc[NCHUNK];
        #pragma unroll
        for (int k = 0; k < NCHUNK; k++) {
            int e = tid + k * 256;
            acc[k] = (e < NC) ? fmaf(__ldcs(nz + e), 0.01f, sb[e] * 0.005f) : 0.0f;
        }

        for (int i = 0; i < n; i++) {
            const float* xr = xb + (size_t)srows[tt][i] * NC;
            float w = sw[tt][i];
            #pragma unroll
            for (int k = 0; k < NCHUNK; k++) {
                int e = tid + k * 256;
                if (e < NC) acc[k] = fmaf(w, __ldg(xr + e), acc[k]);
            }
        }

        #pragma unroll
        for (int k = 0; k < NCHUNK; k++) {
            int e = tid + k * 256;
            if (e < NC) __stcs(ob + e, acc[k]);
        }
    }
}

extern "C" void kernel_launch(void* const* d_in, const int* in_sizes, int n_in,
                              void* d_out, int out_size) {
    const float* x     = (const float*)d_in[0];
    const void*  mask  = d_in[1];
    const void*  keep  = d_in[2];
    const float* bj    = (const float*)d_in[3];
    const float* noise = (const float*)d_in[4];
    const float* sp    = (const float*)d_in[5];
    float* out = (float*)d_out;

    fused_kernel<<<BB * TILES, 256>>>(x, mask, keep, bj, noise, sp, out);
}